// round 2
// baseline (speedup 1.0000x reference)
#include <cuda_runtime.h>
#include <math.h>
#include <float.h>

#define B 1024
#define P 256
#define F_IN 8
#define H 16
#define K 8

// scratch (allocation-free rule: device globals)
__device__ float g_h[B * P * H];     // encoded particle features
__device__ float g_sq[B * P];        // per-particle squared norm

__device__ __forceinline__ float elu_f(float x) {
    return x > 0.0f ? x : expm1f(x);
}

// ---------------- Kernel 1: particle encoder MLP ----------------
__global__ __launch_bounds__(256) void encode_kernel(
    const float* __restrict__ x,
    const float* __restrict__ W1,   // [16,8]
    const float* __restrict__ W2,   // [16,16]
    const float* __restrict__ b2,   // [16]
    const float* __restrict__ W3,   // [16,16]
    const float* __restrict__ b3)   // [16]
{
    __shared__ float sW1[H * F_IN];
    __shared__ float sW2[H * H];
    __shared__ float sW3[H * H];
    __shared__ float sb2[H];
    __shared__ float sb3[H];

    int tid = threadIdx.x;
    if (tid < H * F_IN) sW1[tid] = W1[tid];
    if (tid < H * H)   { sW2[tid] = W2[tid]; sW3[tid] = W3[tid]; }
    if (tid < H)       { sb2[tid] = b2[tid]; sb3[tid] = b3[tid]; }
    __syncthreads();

    int t = blockIdx.x * 256 + tid;          // particle row in [0, B*P)

    const float4* xin = reinterpret_cast<const float4*>(x + (size_t)t * F_IN);
    float4 a0 = xin[0], a1 = xin[1];
    float in[F_IN] = {a0.x, a0.y, a0.z, a0.w, a1.x, a1.y, a1.z, a1.w};

    float h1[H];
#pragma unroll
    for (int o = 0; o < H; o++) {
        float acc = 0.0f;
#pragma unroll
        for (int d = 0; d < F_IN; d++) acc = fmaf(sW1[o * F_IN + d], in[d], acc);
        h1[o] = elu_f(acc);
    }
    float h2[H];
#pragma unroll
    for (int o = 0; o < H; o++) {
        float acc = sb2[o];
#pragma unroll
        for (int d = 0; d < H; d++) acc = fmaf(sW2[o * H + d], h1[d], acc);
        h2[o] = elu_f(acc);
    }
    float h3[H];
    float sq = 0.0f;
#pragma unroll
    for (int o = 0; o < H; o++) {
        float acc = sb3[o];
#pragma unroll
        for (int d = 0; d < H; d++) acc = fmaf(sW3[o * H + d], h2[d], acc);
        h3[o] = elu_f(acc);
    }
    // squared norm with the SAME fma chain order used in the distance dot
    // so that dist(i,i) computes to exactly 0.
#pragma unroll
    for (int d = 0; d < H; d++) sq = fmaf(h3[d], h3[d], sq);

    float4* out4 = reinterpret_cast<float4*>(g_h + (size_t)t * H);
#pragma unroll
    for (int q = 0; q < 4; q++)
        out4[q] = make_float4(h3[q * 4 + 0], h3[q * 4 + 1], h3[q * 4 + 2], h3[q * 4 + 3]);
    g_sq[t] = sq;
}

// ---------------- Kernel 2: per-graph kNN + EdgeConv + pool + head ----------------
#define HP 17   // padded row stride to avoid smem bank conflicts on gathers

__global__ __launch_bounds__(256) void graph_kernel(
    const float* __restrict__ We,   // [16,32]
    const float* __restrict__ be,   // [16]
    const float* __restrict__ Wo1,  // [8,16]
    const float* __restrict__ bo1,  // [8]
    const float* __restrict__ Wo2,  // [1,8]
    const float* __restrict__ bo2,  // [1]
    float* __restrict__ out)        // [B,1]
{
    __shared__ float sh[P * HP];      // h tile, padded
    __shared__ float ssq[P];
    __shared__ float sWe[H * 2 * H];  // 512
    __shared__ float sbe[H];
    __shared__ float sred[8 * H];     // per-warp partial sums
    __shared__ float sp[H];           // pooled

    int tid = threadIdx.x;
    int b   = blockIdx.x;

    // cooperative loads
    {
        const float4* src = reinterpret_cast<const float4*>(g_h + ((size_t)b * P) * H);
        // thread t owns row t: 4 x float4
        float4 r0 = src[tid * 4 + 0];
        float4 r1 = src[tid * 4 + 1];
        float4 r2 = src[tid * 4 + 2];
        float4 r3 = src[tid * 4 + 3];
        float* row = sh + tid * HP;
        row[0]=r0.x; row[1]=r0.y; row[2]=r0.z; row[3]=r0.w;
        row[4]=r1.x; row[5]=r1.y; row[6]=r1.z; row[7]=r1.w;
        row[8]=r2.x; row[9]=r2.y; row[10]=r2.z; row[11]=r2.w;
        row[12]=r3.x; row[13]=r3.y; row[14]=r3.z; row[15]=r3.w;
        ssq[tid] = g_sq[(size_t)b * P + tid];
    }
    // 512 elements, 256 threads: 2 per thread (bug fix: previously only 256 loaded)
    sWe[tid]       = We[tid];
    sWe[tid + 256] = We[tid + 256];
    if (tid < H) sbe[tid] = be[tid];
    __syncthreads();

    // my row into registers
    float myh[H];
    float mysq;
    {
        const float* row = sh + tid * HP;
#pragma unroll
        for (int d = 0; d < H; d++) myh[d] = row[d];
        mysq = ssq[tid];
    }

    // ---- top-K smallest distances (replace-max list) ----
    float bd[K];
    int   bi[K];
#pragma unroll
    for (int k = 0; k < K; k++) { bd[k] = FLT_MAX; bi[k] = 0; }
    float mx = FLT_MAX;

    for (int j = 0; j < P; j++) {
        const float* rj = sh + j * HP;   // same addr all lanes -> broadcast
        float dot = 0.0f;
#pragma unroll
        for (int d = 0; d < H; d++) dot = fmaf(myh[d], rj[d], dot);
        float dist = mysq + ssq[j] - 2.0f * dot;
        if (dist < mx) {
            // evict current max (latest index on ties)
            int am = 0; float m0 = bd[0];
#pragma unroll
            for (int k = 1; k < K; k++) if (bd[k] >= m0) { m0 = bd[k]; am = k; }
            bd[am] = dist; bi[am] = j;
            mx = bd[0];
#pragma unroll
            for (int k = 1; k < K; k++) mx = fmaxf(mx, bd[k]);
        }
    }

    // ---- EdgeConv: m = elu(Wa@xi + Wb@(xj-xi) + be), node = max_k m ----
    float u[H];
#pragma unroll
    for (int o = 0; o < H; o++) {
        float acc = sbe[o];
#pragma unroll
        for (int d = 0; d < H; d++) acc = fmaf(sWe[o * 2 * H + d], myh[d], acc);
        u[o] = acc;
    }
    float node[H];
#pragma unroll
    for (int o = 0; o < H; o++) node[o] = -FLT_MAX;

#pragma unroll
    for (int k = 0; k < K; k++) {
        const float* rj = sh + bi[k] * HP;
        float df[H];
#pragma unroll
        for (int d = 0; d < H; d++) df[d] = rj[d] - myh[d];
#pragma unroll
        for (int o = 0; o < H; o++) {
            float acc = u[o];
#pragma unroll
            for (int d = 0; d < H; d++) acc = fmaf(sWe[o * 2 * H + H + d], df[d], acc);
            node[o] = fmaxf(node[o], elu_f(acc));
        }
    }

    // ---- mean pool over 256 nodes ----
#pragma unroll
    for (int o = 0; o < H; o++) {
        float v = node[o];
#pragma unroll
        for (int off = 16; off >= 1; off >>= 1)
            v += __shfl_xor_sync(0xffffffffu, v, off);
        if ((tid & 31) == 0) sred[(tid >> 5) * H + o] = v;
    }
    __syncthreads();
    if (tid < H) {
        float s = 0.0f;
#pragma unroll
        for (int w = 0; w < 8; w++) s += sred[w * H + tid];
        sp[tid] = s * (1.0f / 256.0f);
    }
    __syncthreads();

    // ---- head MLP + sigmoid (thread 0) ----
    if (tid == 0) {
        float hh[8];
#pragma unroll
        for (int q = 0; q < 8; q++) {
            float acc = bo1[q];
#pragma unroll
            for (int d = 0; d < H; d++) acc = fmaf(Wo1[q * H + d], sp[d], acc);
            hh[q] = elu_f(acc);
        }
        float o2 = bo2[0];
#pragma unroll
        for (int q = 0; q < 8; q++) o2 = fmaf(Wo2[q], hh[q], o2);
        out[b] = 1.0f / (1.0f + expf(-o2));
    }
}

extern "C" void kernel_launch(void* const* d_in, const int* in_sizes, int n_in,
                              void* d_out, int out_size) {
    const float* x   = (const float*)d_in[0];
    const float* W1  = (const float*)d_in[1];
    const float* W2  = (const float*)d_in[2];
    const float* b2  = (const float*)d_in[3];
    const float* W3  = (const float*)d_in[4];
    const float* b3  = (const float*)d_in[5];
    const float* We  = (const float*)d_in[6];
    const float* be  = (const float*)d_in[7];
    const float* Wo1 = (const float*)d_in[8];
    const float* bo1 = (const float*)d_in[9];
    const float* Wo2 = (const float*)d_in[10];
    const float* bo2 = (const float*)d_in[11];

    encode_kernel<<<(B * P) / 256, 256>>>(x, W1, W2, b2, W3, b3);
    graph_kernel<<<B, 256>>>(We, be, Wo1, bo1, Wo2, bo2, (float*)d_out);
}

// round 3
// speedup vs baseline: 2.2450x; 2.2450x over previous
#include <cuda_runtime.h>
#include <math.h>
#include <float.h>

#define B 1024
#define P 256
#define F_IN 8
#define H 16
#define K 8

// scratch (allocation-free rule: device globals)
__device__ float g_h[B * P * H];     // encoded particle features
__device__ float g_sq[B * P];        // per-particle squared norm

__device__ __forceinline__ float elu_f(float x) {
    return x > 0.0f ? x : expm1f(x);
}

// packed fp32x2 helpers (Blackwell FFMA2)
__device__ __forceinline__ unsigned long long ffma2(unsigned long long a,
                                                    unsigned long long b,
                                                    unsigned long long c) {
    unsigned long long d;
    asm("fma.rn.f32x2 %0, %1, %2, %3;" : "=l"(d) : "l"(a), "l"(b), "l"(c));
    return d;
}
__device__ __forceinline__ unsigned long long pack2(float lo, float hi) {
    unsigned long long v;
    asm("mov.b64 %0, {%1, %2};" : "=l"(v) : "f"(lo), "f"(hi));
    return v;
}
__device__ __forceinline__ void unpack2(unsigned long long v, float& lo, float& hi) {
    asm("mov.b64 {%0, %1}, %2;" : "=f"(lo), "=f"(hi) : "l"(v));
}

// ---------------- Kernel 1: particle encoder MLP ----------------
__global__ __launch_bounds__(256) void encode_kernel(
    const float* __restrict__ x,
    const float* __restrict__ W1,   // [16,8]
    const float* __restrict__ W2,   // [16,16]
    const float* __restrict__ b2,   // [16]
    const float* __restrict__ W3,   // [16,16]
    const float* __restrict__ b3)   // [16]
{
    __shared__ float sW1[H * F_IN];
    __shared__ float sW2[H * H];
    __shared__ float sW3[H * H];
    __shared__ float sb2[H];
    __shared__ float sb3[H];

    int tid = threadIdx.x;
    if (tid < H * F_IN) sW1[tid] = W1[tid];
    if (tid < H * H)   { sW2[tid] = W2[tid]; sW3[tid] = W3[tid]; }
    if (tid < H)       { sb2[tid] = b2[tid]; sb3[tid] = b3[tid]; }
    __syncthreads();

    int t = blockIdx.x * 256 + tid;          // particle row in [0, B*P)

    const float4* xin = reinterpret_cast<const float4*>(x + (size_t)t * F_IN);
    float4 a0 = xin[0], a1 = xin[1];
    float in[F_IN] = {a0.x, a0.y, a0.z, a0.w, a1.x, a1.y, a1.z, a1.w};

    float h1[H];
#pragma unroll
    for (int o = 0; o < H; o++) {
        float acc = 0.0f;
#pragma unroll
        for (int d = 0; d < F_IN; d++) acc = fmaf(sW1[o * F_IN + d], in[d], acc);
        h1[o] = elu_f(acc);
    }
    float h2[H];
#pragma unroll
    for (int o = 0; o < H; o++) {
        float acc = sb2[o];
#pragma unroll
        for (int d = 0; d < H; d++) acc = fmaf(sW2[o * H + d], h1[d], acc);
        h2[o] = elu_f(acc);
    }
    float h3[H];
#pragma unroll
    for (int o = 0; o < H; o++) {
        float acc = sb3[o];
#pragma unroll
        for (int d = 0; d < H; d++) acc = fmaf(sW3[o * H + d], h2[d], acc);
        h3[o] = elu_f(acc);
    }
    // squared norm in the SAME even/odd packed order as the graph kernel's
    // f32x2 dot chain, so dist(i,i) computes to exactly 0.
    float sq0 = 0.0f, sq1 = 0.0f;
#pragma unroll
    for (int p = 0; p < 8; p++) {
        sq0 = fmaf(h3[2 * p],     h3[2 * p],     sq0);
        sq1 = fmaf(h3[2 * p + 1], h3[2 * p + 1], sq1);
    }
    float sq = sq0 + sq1;

    float4* out4 = reinterpret_cast<float4*>(g_h + (size_t)t * H);
#pragma unroll
    for (int q = 0; q < 4; q++)
        out4[q] = make_float4(h3[q * 4 + 0], h3[q * 4 + 1], h3[q * 4 + 2], h3[q * 4 + 3]);
    g_sq[t] = sq;
}

// ---------------- Kernel 2: per-graph kNN + EdgeConv + pool + head ----------------
__global__ __launch_bounds__(256, 2) void graph_kernel(
    const float* __restrict__ We,   // [16,32]  row o = [Wa_o (16) | Wb_o (16)]
    const float* __restrict__ be,   // [16]
    const float* __restrict__ Wo1,  // [8,16]
    const float* __restrict__ bo1,  // [8]
    const float* __restrict__ Wo2,  // [1,8]
    const float* __restrict__ bo2,  // [1]
    float* __restrict__ out)        // [B,1]
{
    __shared__ __align__(16) float sh[P * H];    // h tile (row stride 16 floats = 64B)
    __shared__ __align__(16) float sz[P * H];    // z[j] = Wb @ h_j
    __shared__ float ssq[P];
    __shared__ __align__(16) float sWb[H * H];   // Wb
    __shared__ __align__(16) float sWd[H * H];   // Wa - Wb
    __shared__ float sbe[H];
    __shared__ float sred[8 * H];
    __shared__ float sp[H];

    int tid = threadIdx.x;
    int b   = blockIdx.x;

    // ---- cooperative loads ----
    float4 r0, r1, r2, r3;
    {
        const float4* src = reinterpret_cast<const float4*>(g_h + ((size_t)b * P) * H);
        r0 = src[tid * 4 + 0];
        r1 = src[tid * 4 + 1];
        r2 = src[tid * 4 + 2];
        r3 = src[tid * 4 + 3];
        float4* dst = reinterpret_cast<float4*>(sh + tid * H);
        dst[0] = r0; dst[1] = r1; dst[2] = r2; dst[3] = r3;
        ssq[tid] = g_sq[(size_t)b * P + tid];
    }
    {
        int o = tid >> 4, d = tid & 15;          // 256 threads = 16x16
        float wa = We[o * 2 * H + d];
        float wb = We[o * 2 * H + H + d];
        sWb[o * H + d] = wb;
        sWd[o * H + d] = wa - wb;
    }
    if (tid < H) sbe[tid] = be[tid];
    float mysq = ssq[tid];  // value also in register path below
    __syncthreads();
    mysq = ssq[tid];

    // pack my row for f32x2
    unsigned long long myh2[8];
    myh2[0] = pack2(r0.x, r0.y); myh2[1] = pack2(r0.z, r0.w);
    myh2[2] = pack2(r1.x, r1.y); myh2[3] = pack2(r1.z, r1.w);
    myh2[4] = pack2(r2.x, r2.y); myh2[5] = pack2(r2.z, r2.w);
    myh2[6] = pack2(r3.x, r3.y); myh2[7] = pack2(r3.z, r3.w);

    // ---- z row: z[o] = Wb_o . myh  (per-particle, shared by all queries) ----
    {
        float zv[H];
#pragma unroll
        for (int o = 0; o < H; o++) {
            const unsigned long long* w =
                reinterpret_cast<const unsigned long long*>(sWb + o * H);
            unsigned long long acc = 0ull;
#pragma unroll
            for (int p = 0; p < 8; p++) acc = ffma2(myh2[p], w[p], acc);
            float lo, hi; unpack2(acc, lo, hi);
            zv[o] = lo + hi;
        }
        float4* zdst = reinterpret_cast<float4*>(sz + tid * H);
#pragma unroll
        for (int q = 0; q < 4; q++)
            zdst[q] = make_float4(zv[q * 4 + 0], zv[q * 4 + 1], zv[q * 4 + 2], zv[q * 4 + 3]);
    }
    __syncthreads();

    // ---- top-K smallest distances, packed u32 keys: (sortable_dist & ~0xFF) | j ----
    unsigned int keys[K];
#pragma unroll
    for (int k = 0; k < K; k++) keys[k] = 0xFFFFFF00u | (unsigned)k;
    unsigned int kmax = 0xFFFFFF00u | 7u;

    for (int j = 0; j < P; j += 2) {
        const ulonglong2* ra = reinterpret_cast<const ulonglong2*>(sh + j * H);
        ulonglong2 a0 = ra[0], a1 = ra[1], a2 = ra[2], a3 = ra[3];
        ulonglong2 c0 = ra[4], c1 = ra[5], c2 = ra[6], c3 = ra[7];

        unsigned long long accA = 0ull, accB = 0ull;
        accA = ffma2(myh2[0], a0.x, accA); accB = ffma2(myh2[0], c0.x, accB);
        accA = ffma2(myh2[1], a0.y, accA); accB = ffma2(myh2[1], c0.y, accB);
        accA = ffma2(myh2[2], a1.x, accA); accB = ffma2(myh2[2], c1.x, accB);
        accA = ffma2(myh2[3], a1.y, accA); accB = ffma2(myh2[3], c1.y, accB);
        accA = ffma2(myh2[4], a2.x, accA); accB = ffma2(myh2[4], c2.x, accB);
        accA = ffma2(myh2[5], a2.y, accA); accB = ffma2(myh2[5], c2.y, accB);
        accA = ffma2(myh2[6], a3.x, accA); accB = ffma2(myh2[6], c3.x, accB);
        accA = ffma2(myh2[7], a3.y, accA); accB = ffma2(myh2[7], c3.y, accB);

        float loA, hiA, loB, hiB;
        unpack2(accA, loA, hiA); unpack2(accB, loB, hiB);
        float dotA = loA + hiA, dotB = loB + hiB;
        float distA = fmaf(-2.0f, dotA, mysq + ssq[j]);
        float distB = fmaf(-2.0f, dotB, mysq + ssq[j + 1]);

        unsigned int uA = __float_as_uint(distA);
        uA ^= (unsigned int)((int)uA >> 31) | 0x80000000u;
        unsigned int keyA = (uA & 0xFFFFFF00u) | (unsigned)j;
        unsigned int uB = __float_as_uint(distB);
        uB ^= (unsigned int)((int)uB >> 31) | 0x80000000u;
        unsigned int keyB = (uB & 0xFFFFFF00u) | (unsigned)(j + 1);

        bool candA = keyA < kmax;
        bool candB = keyB < kmax;
        if (__any_sync(0xffffffffu, candA | candB)) {   // warp-uniform branch
            // insert A (re-check against current kmax)
            {
                bool a = keyA < kmax;
#pragma unroll
                for (int k = 0; k < K; k++) {
                    bool r = a && (keys[k] == kmax);
                    keys[k] = r ? keyA : keys[k];
                }
                unsigned int t = keys[0];
#pragma unroll
                for (int k = 1; k < K; k++) t = max(t, keys[k]);
                kmax = t;
            }
            // insert B
            {
                bool a = keyB < kmax;
#pragma unroll
                for (int k = 0; k < K; k++) {
                    bool r = a && (keys[k] == kmax);
                    keys[k] = r ? keyB : keys[k];
                }
                unsigned int t = keys[0];
#pragma unroll
                for (int k = 1; k < K; k++) t = max(t, keys[k]);
                kmax = t;
            }
        }
    }

    // ---- EdgeConv via precomputed z: node = elu(be + (Wa-Wb).xi + max_k z[jk]) ----
    float best[H];
#pragma unroll
    for (int o = 0; o < H; o++) best[o] = -FLT_MAX;
#pragma unroll
    for (int k = 0; k < K; k++) {
        int j = (int)(keys[k] & 0xFFu);
        const float4* zr = reinterpret_cast<const float4*>(sz + j * H);
        float4 z0 = zr[0], z1 = zr[1], z2 = zr[2], z3 = zr[3];
        best[0]  = fmaxf(best[0],  z0.x); best[1]  = fmaxf(best[1],  z0.y);
        best[2]  = fmaxf(best[2],  z0.z); best[3]  = fmaxf(best[3],  z0.w);
        best[4]  = fmaxf(best[4],  z1.x); best[5]  = fmaxf(best[5],  z1.y);
        best[6]  = fmaxf(best[6],  z1.z); best[7]  = fmaxf(best[7],  z1.w);
        best[8]  = fmaxf(best[8],  z2.x); best[9]  = fmaxf(best[9],  z2.y);
        best[10] = fmaxf(best[10], z2.z); best[11] = fmaxf(best[11], z2.w);
        best[12] = fmaxf(best[12], z3.x); best[13] = fmaxf(best[13], z3.y);
        best[14] = fmaxf(best[14], z3.z); best[15] = fmaxf(best[15], z3.w);
    }

    float node[H];
#pragma unroll
    for (int o = 0; o < H; o++) {
        const unsigned long long* w =
            reinterpret_cast<const unsigned long long*>(sWd + o * H);
        unsigned long long acc = 0ull;
#pragma unroll
        for (int p = 0; p < 8; p++) acc = ffma2(myh2[p], w[p], acc);
        float lo, hi; unpack2(acc, lo, hi);
        node[o] = elu_f(sbe[o] + (lo + hi) + best[o]);
    }

    // ---- mean pool over 256 nodes ----
#pragma unroll
    for (int o = 0; o < H; o++) {
        float v = node[o];
#pragma unroll
        for (int off = 16; off >= 1; off >>= 1)
            v += __shfl_xor_sync(0xffffffffu, v, off);
        if ((tid & 31) == 0) sred[(tid >> 5) * H + o] = v;
    }
    __syncthreads();
    if (tid < H) {
        float s = 0.0f;
#pragma unroll
        for (int w = 0; w < 8; w++) s += sred[w * H + tid];
        sp[tid] = s * (1.0f / 256.0f);
    }
    __syncthreads();

    // ---- head MLP + sigmoid (first warp, 8 lanes) ----
    if (tid < 32) {
        float hv = 0.0f;
        if (tid < 8) {
            float acc = bo1[tid];
#pragma unroll
            for (int d = 0; d < H; d++) acc = fmaf(Wo1[tid * H + d], sp[d], acc);
            hv = elu_f(acc) * Wo2[tid];
        }
#pragma unroll
        for (int off = 4; off >= 1; off >>= 1)
            hv += __shfl_xor_sync(0xffffffffu, hv, off);
        if (tid == 0) out[b] = 1.0f / (1.0f + expf(-(hv + bo2[0])));
    }
}

extern "C" void kernel_launch(void* const* d_in, const int* in_sizes, int n_in,
                              void* d_out, int out_size) {
    const float* x   = (const float*)d_in[0];
    const float* W1  = (const float*)d_in[1];
    const float* W2  = (const float*)d_in[2];
    const float* b2  = (const float*)d_in[3];
    const float* W3  = (const float*)d_in[4];
    const float* b3  = (const float*)d_in[5];
    const float* We  = (const float*)d_in[6];
    const float* be  = (const float*)d_in[7];
    const float* Wo1 = (const float*)d_in[8];
    const float* bo1 = (const float*)d_in[9];
    const float* Wo2 = (const float*)d_in[10];
    const float* bo2 = (const float*)d_in[11];

    encode_kernel<<<(B * P) / 256, 256>>>(x, W1, W2, b2, W3, b3);
    graph_kernel<<<B, 256>>>(We, be, Wo1, bo1, Wo2, bo2, (float*)d_out);
}

// round 4
// speedup vs baseline: 2.8902x; 1.2874x over previous
#include <cuda_runtime.h>
#include <math.h>
#include <float.h>

#define B 1024
#define P 256
#define F_IN 8
#define H 16
#define K 8

__device__ __forceinline__ float elu_f(float x) {
    return x > 0.0f ? x : expm1f(x);
}

// packed fp32x2 helpers (Blackwell FFMA2)
__device__ __forceinline__ unsigned long long ffma2(unsigned long long a,
                                                    unsigned long long b,
                                                    unsigned long long c) {
    unsigned long long d;
    asm("fma.rn.f32x2 %0, %1, %2, %3;" : "=l"(d) : "l"(a), "l"(b), "l"(c));
    return d;
}
__device__ __forceinline__ unsigned long long pack2(float lo, float hi) {
    unsigned long long v;
    asm("mov.b64 %0, {%1, %2};" : "=l"(v) : "f"(lo), "f"(hi));
    return v;
}
__device__ __forceinline__ void unpack2(unsigned long long v, float& lo, float& hi) {
    asm("mov.b64 {%0, %1}, %2;" : "=f"(lo), "=f"(hi) : "l"(v));
}

// branchless sorted insert: keys ascending; largest falls off the end.
__device__ __forceinline__ void insert8(unsigned int (&s)[K], unsigned int x) {
    unsigned int t = x;
#pragma unroll
    for (int k = 0; k < K; k++) {
        unsigned int lo = umin(s[k], t);
        t = umax(s[k], t);
        s[k] = lo;
    }
}

// ---------------- Fused kernel: encode + kNN + EdgeConv + pool + head ----------------
__global__ __launch_bounds__(256, 2) void fused_kernel(
    const float* __restrict__ x,    // [B, P*F_IN]
    const float* __restrict__ W1,   // [16,8]
    const float* __restrict__ W2,   // [16,16]
    const float* __restrict__ b2,   // [16]
    const float* __restrict__ W3,   // [16,16]
    const float* __restrict__ b3,   // [16]
    const float* __restrict__ We,   // [16,32] row o = [Wa_o | Wb_o]
    const float* __restrict__ be,   // [16]
    const float* __restrict__ Wo1,  // [8,16]
    const float* __restrict__ bo1,  // [8]
    const float* __restrict__ Wo2,  // [1,8]
    const float* __restrict__ bo2,  // [1]
    float* __restrict__ out)        // [B,1]
{
    __shared__ __align__(16) float sh[P * H];    // h tile
    __shared__ __align__(16) float sz[P * H];    // z[j] = Wb @ h_j
    __shared__ float ssq[P];
    __shared__ __align__(16) float sW1[H * F_IN];
    __shared__ __align__(16) float sW2[H * H];
    __shared__ __align__(16) float sW3[H * H];
    __shared__ __align__(16) float sWb[H * H];   // Wb
    __shared__ __align__(16) float sWd[H * H];   // Wa - Wb
    __shared__ float sb2[H], sb3[H], sbe[H];
    __shared__ float sred[8 * H];
    __shared__ float sp[H];

    int tid = threadIdx.x;
    int b   = blockIdx.x;

    // ---- phase 0: cooperative weight staging ----
    if (tid < H * F_IN) sW1[tid] = W1[tid];
    if (tid < H * H)   { sW2[tid] = W2[tid]; sW3[tid] = W3[tid]; }
    if (tid < H)       { sb2[tid] = b2[tid]; sb3[tid] = b3[tid]; sbe[tid] = be[tid]; }
    {
        int o = tid >> 4, d = tid & 15;          // 256 threads = 16x16
        float wa = We[o * 2 * H + d];
        float wb = We[o * 2 * H + H + d];
        sWb[o * H + d] = wb;
        sWd[o * H + d] = wa - wb;
    }
    __syncthreads();

    // ---- phase 1: encode my particle ----
    float h3[H];
    float mysq;
    {
        const float4* xin = reinterpret_cast<const float4*>(
            x + ((size_t)b * P + tid) * F_IN);
        float4 a0 = xin[0], a1 = xin[1];
        float in[F_IN] = {a0.x, a0.y, a0.z, a0.w, a1.x, a1.y, a1.z, a1.w};

        float h1[H];
#pragma unroll
        for (int o = 0; o < H; o++) {
            float acc = 0.0f;
#pragma unroll
            for (int d = 0; d < F_IN; d++) acc = fmaf(sW1[o * F_IN + d], in[d], acc);
            h1[o] = elu_f(acc);
        }
        float h2[H];
#pragma unroll
        for (int o = 0; o < H; o++) {
            float acc = sb2[o];
#pragma unroll
            for (int d = 0; d < H; d++) acc = fmaf(sW2[o * H + d], h1[d], acc);
            h2[o] = elu_f(acc);
        }
#pragma unroll
        for (int o = 0; o < H; o++) {
            float acc = sb3[o];
#pragma unroll
            for (int d = 0; d < H; d++) acc = fmaf(sW3[o * H + d], h2[d], acc);
            h3[o] = elu_f(acc);
        }
        // squared norm in SAME even/odd packed order as the f32x2 dot chain,
        // so dist(i,i) is exactly 0 bitwise.
        float sq0 = 0.0f, sq1 = 0.0f;
#pragma unroll
        for (int p = 0; p < 8; p++) {
            sq0 = fmaf(h3[2 * p],     h3[2 * p],     sq0);
            sq1 = fmaf(h3[2 * p + 1], h3[2 * p + 1], sq1);
        }
        mysq = sq0 + sq1;
    }

    // pack my row for f32x2
    unsigned long long myh2[8];
#pragma unroll
    for (int p = 0; p < 8; p++) myh2[p] = pack2(h3[2 * p], h3[2 * p + 1]);

    // ---- phase 2: publish h, sq, z = Wb @ h (own particle) ----
    {
        float4* dst = reinterpret_cast<float4*>(sh + tid * H);
#pragma unroll
        for (int q = 0; q < 4; q++)
            dst[q] = make_float4(h3[q * 4 + 0], h3[q * 4 + 1], h3[q * 4 + 2], h3[q * 4 + 3]);
        ssq[tid] = mysq;

        float zv[H];
#pragma unroll
        for (int o = 0; o < H; o++) {
            const unsigned long long* w =
                reinterpret_cast<const unsigned long long*>(sWb + o * H);
            unsigned long long acc = 0ull;
#pragma unroll
            for (int p = 0; p < 8; p++) acc = ffma2(myh2[p], w[p], acc);
            float lo, hi; unpack2(acc, lo, hi);
            zv[o] = lo + hi;
        }
        float4* zdst = reinterpret_cast<float4*>(sz + tid * H);
#pragma unroll
        for (int q = 0; q < 4; q++)
            zdst[q] = make_float4(zv[q * 4 + 0], zv[q * 4 + 1], zv[q * 4 + 2], zv[q * 4 + 3]);
    }
    __syncthreads();

    // ---- phase 3: top-K smallest distances, sorted-cascade, branchless ----
    unsigned int keys[K];
#pragma unroll
    for (int k = 0; k < K; k++) keys[k] = 0xFFFFFFFFu;

    const float2* sq2 = reinterpret_cast<const float2*>(ssq);

#pragma unroll 4
    for (int j = 0; j < P; j += 2) {
        const ulonglong2* ra = reinterpret_cast<const ulonglong2*>(sh + j * H);
        ulonglong2 a0 = ra[0], a1 = ra[1], a2 = ra[2], a3 = ra[3];
        ulonglong2 c0 = ra[4], c1 = ra[5], c2 = ra[6], c3 = ra[7];
        float2 sj = sq2[j >> 1];

        unsigned long long accA = 0ull, accB = 0ull;
        accA = ffma2(myh2[0], a0.x, accA); accB = ffma2(myh2[0], c0.x, accB);
        accA = ffma2(myh2[1], a0.y, accA); accB = ffma2(myh2[1], c0.y, accB);
        accA = ffma2(myh2[2], a1.x, accA); accB = ffma2(myh2[2], c1.x, accB);
        accA = ffma2(myh2[3], a1.y, accA); accB = ffma2(myh2[3], c1.y, accB);
        accA = ffma2(myh2[4], a2.x, accA); accB = ffma2(myh2[4], c2.x, accB);
        accA = ffma2(myh2[5], a2.y, accA); accB = ffma2(myh2[5], c2.y, accB);
        accA = ffma2(myh2[6], a3.x, accA); accB = ffma2(myh2[6], c3.x, accB);
        accA = ffma2(myh2[7], a3.y, accA); accB = ffma2(myh2[7], c3.y, accB);

        float loA, hiA, loB, hiB;
        unpack2(accA, loA, hiA); unpack2(accB, loB, hiB);
        float distA = fmaf(-2.0f, loA + hiA, mysq + sj.x);
        float distB = fmaf(-2.0f, loB + hiB, mysq + sj.y);
        // clamp: exact-zero self stays 0; tiny negative rounding -> +0 (kept).
        // positive float bits are uint-ordered, so no sign transform needed.
        unsigned int uA = __float_as_uint(fmaxf(distA, 0.0f));
        unsigned int uB = __float_as_uint(fmaxf(distB, 0.0f));
        insert8(keys, (uA & 0xFFFFFF00u) | (unsigned)j);
        insert8(keys, (uB & 0xFFFFFF00u) | (unsigned)(j + 1));
    }

    // ---- phase 4: EdgeConv  node = elu(be + (Wa-Wb).xi + max_k z[jk]) ----
    float best[H];
#pragma unroll
    for (int o = 0; o < H; o++) best[o] = -FLT_MAX;
#pragma unroll
    for (int k = 0; k < K; k++) {
        int j = (int)(keys[k] & 0xFFu);
        const float4* zr = reinterpret_cast<const float4*>(sz + j * H);
        float4 z0 = zr[0], z1 = zr[1], z2 = zr[2], z3 = zr[3];
        best[0]  = fmaxf(best[0],  z0.x); best[1]  = fmaxf(best[1],  z0.y);
        best[2]  = fmaxf(best[2],  z0.z); best[3]  = fmaxf(best[3],  z0.w);
        best[4]  = fmaxf(best[4],  z1.x); best[5]  = fmaxf(best[5],  z1.y);
        best[6]  = fmaxf(best[6],  z1.z); best[7]  = fmaxf(best[7],  z1.w);
        best[8]  = fmaxf(best[8],  z2.x); best[9]  = fmaxf(best[9],  z2.y);
        best[10] = fmaxf(best[10], z2.z); best[11] = fmaxf(best[11], z2.w);
        best[12] = fmaxf(best[12], z3.x); best[13] = fmaxf(best[13], z3.y);
        best[14] = fmaxf(best[14], z3.z); best[15] = fmaxf(best[15], z3.w);
    }

    float node[H];
#pragma unroll
    for (int o = 0; o < H; o++) {
        const unsigned long long* w =
            reinterpret_cast<const unsigned long long*>(sWd + o * H);
        unsigned long long acc = 0ull;
#pragma unroll
        for (int p = 0; p < 8; p++) acc = ffma2(myh2[p], w[p], acc);
        float lo, hi; unpack2(acc, lo, hi);
        node[o] = elu_f(sbe[o] + (lo + hi) + best[o]);
    }

    // ---- phase 5: mean pool over 256 nodes ----
#pragma unroll
    for (int o = 0; o < H; o++) {
        float v = node[o];
#pragma unroll
        for (int off = 16; off >= 1; off >>= 1)
            v += __shfl_xor_sync(0xffffffffu, v, off);
        if ((tid & 31) == 0) sred[(tid >> 5) * H + o] = v;
    }
    __syncthreads();
    if (tid < H) {
        float s = 0.0f;
#pragma unroll
        for (int w = 0; w < 8; w++) s += sred[w * H + tid];
        sp[tid] = s * (1.0f / 256.0f);
    }
    __syncthreads();

    // ---- phase 6: head MLP + sigmoid (first warp) ----
    if (tid < 32) {
        float hv = 0.0f;
        if (tid < 8) {
            float acc = bo1[tid];
#pragma unroll
            for (int d = 0; d < H; d++) acc = fmaf(Wo1[tid * H + d], sp[d], acc);
            hv = elu_f(acc) * Wo2[tid];
        }
#pragma unroll
        for (int off = 4; off >= 1; off >>= 1)
            hv += __shfl_xor_sync(0xffffffffu, hv, off);
        if (tid == 0) out[b] = 1.0f / (1.0f + expf(-(hv + bo2[0])));
    }
}

extern "C" void kernel_launch(void* const* d_in, const int* in_sizes, int n_in,
                              void* d_out, int out_size) {
    const float* x   = (const float*)d_in[0];
    const float* W1  = (const float*)d_in[1];
    const float* W2  = (const float*)d_in[2];
    const float* b2  = (const float*)d_in[3];
    const float* W3  = (const float*)d_in[4];
    const float* b3  = (const float*)d_in[5];
    const float* We  = (const float*)d_in[6];
    const float* be  = (const float*)d_in[7];
    const float* Wo1 = (const float*)d_in[8];
    const float* bo1 = (const float*)d_in[9];
    const float* Wo2 = (const float*)d_in[10];
    const float* bo2 = (const float*)d_in[11];

    fused_kernel<<<B, 256>>>(x, W1, W2, b2, W3, b3, We, be,
                             Wo1, bo1, Wo2, bo2, (float*)d_out);
}